// round 13
// baseline (speedup 1.0000x reference)
#include <cuda_runtime.h>
#include <cuda_fp16.h>
#include <cstdint>

#define DIM     256
#define NEMBED  512
#define NROWS   131072
#define OUT_ELEMS 33554432
#define LOSS_OFF  33554432
#define IND_OFF   33554433

#define BM 256
#define NCTA (NROWS / BM)         // 512
#define PANEL 32
#define NPANEL (NEMBED / PANEL)   // 16
#define KLD 264                   // halves per row; 528B stride
#define SCALE 2048.0f             // 2^11
#define INV_SCALE2 2.38418579e-07f // 2^-22 exact
#define NTHREADS 1024
#define MAXCAND 16

#define ROWB (KLD * 2)            // 528 B
#define OFF_AHI  0                                   // 256*528 = 135168
#define OFF_B    (OFF_AHI + BM * ROWB)               // 135168
#define BSTAGE   (PANEL * ROWB)                      // 16896
#define OFF_SSQ  (OFF_B + 2 * BSTAGE)                // 168960 (512 f)
#define OFF_RSSQ (OFF_SSQ + NEMBED * 4)              // 171008 (256 f)
#define OFF_CIDX (OFF_RSSQ + BM * 4)                 // 172032 (256*16 i)
#define OFF_CCNT (OFF_CIDX + BM * MAXCAND * 4)       // 188416 (256 i)
#define OFF_BEST (OFF_CCNT + BM * 4)                 // 189440 (256 i)
#define OFF_RED  (OFF_BEST + BM * 4)                 // 190464 (32 f)
#define SMEM_BYTES (OFF_RED + 128)                   // 190592

__device__ float  g_embed_n[NEMBED * DIM];
__device__ __half g_bh16[NEMBED * DIM];
__device__ float  g_ssq[NEMBED];
__device__ float  g_diff_arr[NCTA];
__device__ unsigned g_count;      // static-init 0; last CTA resets to 0

__device__ __forceinline__ uint32_t smem_u32(const void* p) {
    uint32_t a;
    asm("{ .reg .u64 t; cvta.to.shared.u64 t, %1; cvt.u32.u64 %0, t; }" : "=r"(a) : "l"(p));
    return a;
}
__device__ __forceinline__ void mma_f16(float* d, uint32_t a0, uint32_t a1,
                                        uint32_t a2, uint32_t a3,
                                        uint32_t b0, uint32_t b1) {
    asm volatile(
        "mma.sync.aligned.m16n8k16.row.col.f32.f16.f16.f32 "
        "{%0,%1,%2,%3}, {%4,%5,%6,%7}, {%8,%9}, {%0,%1,%2,%3};"
        : "+f"(d[0]), "+f"(d[1]), "+f"(d[2]), "+f"(d[3])
        : "r"(a0), "r"(a1), "r"(a2), "r"(a3), "r"(b0), "r"(b1));
}
__device__ __forceinline__ void ldsm4(uint32_t& r0, uint32_t& r1,
                                      uint32_t& r2, uint32_t& r3, uint32_t addr) {
    asm volatile("ldmatrix.sync.aligned.m8n8.x4.shared.b16 {%0,%1,%2,%3}, [%4];"
                 : "=r"(r0), "=r"(r1), "=r"(r2), "=r"(r3) : "r"(addr));
}
__device__ __forceinline__ void cp16(uint32_t dst, const void* src) {
    asm volatile("cp.async.cg.shared.global [%0], [%1], 16;" :: "r"(dst), "l"(src) : "memory");
}
#define CP_COMMIT() asm volatile("cp.async.commit_group;" ::: "memory")
#define CP_WAIT0()  asm volatile("cp.async.wait_group 0;" ::: "memory")

// ------------------------------------- normalize + fp16 hi (scaled) ----
__global__ void normalize_kernel(const float* __restrict__ emb) {
    __shared__ float w[8];
    int r = blockIdx.x, t = threadIdx.x;
    float v = emb[r * DIM + t];
    float s = v * v;
    #pragma unroll
    for (int o = 16; o > 0; o >>= 1) s += __shfl_xor_sync(0xffffffffu, s, o);
    if ((t & 31) == 0) w[t >> 5] = s;
    __syncthreads();
    float sum = 0.0f;
    #pragma unroll
    for (int k = 0; k < 8; ++k) sum += w[k];
    float en = __fdiv_rn(v, __fsqrt_rn(sum));
    g_embed_n[r * DIM + t] = en;
    g_bh16[r * DIM + t] = __float2half_rn(en * SCALE);

    float s2 = en * en;
    #pragma unroll
    for (int o = 16; o > 0; o >>= 1) s2 += __shfl_xor_sync(0xffffffffu, s2, o);
    __syncthreads();
    if ((t & 31) == 0) w[t >> 5] = s2;
    __syncthreads();
    if (t == 0) {
        float tot = 0.0f;
        #pragma unroll
        for (int k = 0; k < 8; ++k) tot += w[k];
        g_ssq[r] = tot;
    }
}

// ------------------------------------------------------------- main ----
__global__ void __launch_bounds__(NTHREADS, 1)
main_kernel(const float* __restrict__ input,
            float* __restrict__ out,
            float* __restrict__ ind_out,
            float* __restrict__ loss_out) {
    extern __shared__ char sm[];
    const uint32_t smb = smem_u32(sm);
    __half* ahi   = (__half*)(sm + OFF_AHI);
    float*  ssq_s = (float*)(sm + OFF_SSQ);
    float*  rssq_s= (float*)(sm + OFF_RSSQ);
    int*    cidx  = (int*)(sm + OFF_CIDX);
    int*    ccnt  = (int*)(sm + OFF_CCNT);
    int*    best_s= (int*)(sm + OFF_BEST);
    float*  red   = (float*)(sm + OFF_RED);

    const int tid = threadIdx.x;
    const int wid = tid >> 5;
    const int lid = tid & 31;
    const int lq  = lid >> 2;
    const int lr  = lid & 3;
    const int wm  = wid & 15;     // M warp: rows 16*wm..16*wm+15
    const int wn  = wid >> 4;     // N half: codes 16*wn..16*wn+15 of each panel
    const size_t n0 = (size_t)blockIdx.x * BM;

    // ---- prefetch B panel 0 (hi) into stage 0: 1024 chunks, 1 iter ----
    {
        int r = tid >> 5, ch = tid & 31;
        cp16(smb + OFF_B + r * ROWB + ch * 16, g_bh16 + r * DIM + ch * 8);
        CP_COMMIT();
    }

    // ---- load input tile (256 rows), scale, fp16 hi split ----
    #pragma unroll
    for (int i = 0; i < 16; ++i) {
        int slot = tid + i * NTHREADS;           // 0..16383
        int m = slot >> 6, c4 = slot & 63;
        float4 v = *(const float4*)(input + (n0 + m) * DIM + c4 * 4);
        __half hx = __float2half_rn(v.x * SCALE);
        __half hy = __float2half_rn(v.y * SCALE);
        __half hz = __float2half_rn(v.z * SCALE);
        __half hw = __float2half_rn(v.w * SCALE);
        int ho = m * KLD + c4 * 4;
        *(__half2*)(ahi + ho)     = __halves2half2(hx, hy);
        *(__half2*)(ahi + ho + 2) = __halves2half2(hz, hw);
    }
    if (tid < 512) ssq_s[tid] = g_ssq[tid];
    if (tid < BM) ccnt[tid] = 0;

    // ---- per-row ||x||^2 — threads 0..511, IDENTICAL arithmetic order ----
    if (tid < 512) {
        int m = tid >> 1, half = tid & 1;        // 256 rows
        const float* xr = input + (n0 + m) * DIM + half * 128;
        float s = 0.0f;
        #pragma unroll 8
        for (int k4 = 0; k4 < 32; ++k4) {
            float4 v = *(const float4*)(xr + k4 * 4);
            s += v.x * v.x;
            s += v.y * v.y;
            s += v.z * v.z;
            s += v.w * v.w;
        }
        s += __shfl_xor_sync(0xffffffffu, s, 1);
        if (half == 0) rssq_s[m] = s;
    }
    __syncthreads();

    const int r0 = wm * 16 + lq;
    // gate width: >2x the rigorous 1-term error bound
    const float w0 = 0.0025f * __fsqrt_rn(rssq_s[r0])     + 0.003f;
    const float w1 = 0.0025f * __fsqrt_rn(rssq_s[r0 + 8]) + 0.003f;

    // ---- ldmatrix addresses ----
    const int rowin = lid & 7;
    const int mi    = lid >> 3;
    const int aRow  = wm * 16 + rowin + 8 * (mi & 1);
    const uint32_t aHiA = smb + OFF_AHI + (uint32_t)(aRow * ROWB + (mi >> 1) * 16);
    // one ldsm4 covers both n8 tiles of this warp's 16-code group
    const uint32_t bOff = (uint32_t)((8 * (2 * wn + (mi >> 1)) + rowin) * ROWB + (mi & 1) * 16);

    float bv0 = -3.4e38f, bv1 = -3.4e38f;

    for (int p = 0; p < NPANEL; ++p) {
        CP_WAIT0();
        __syncthreads();
        if (p + 1 < NPANEL) {
            const int np = p + 1, st = np & 1;
            int r = tid >> 5, ch = tid & 31;
            cp16(smb + OFF_B + st * BSTAGE + r * ROWB + ch * 16,
                 g_bh16 + (np * PANEL + r) * DIM + ch * 8);
            CP_COMMIT();
        }

        const uint32_t sbh = smb + OFF_B + (p & 1) * BSTAGE;

        float acc[2][4];
        #pragma unroll
        for (int j = 0; j < 2; ++j)
            #pragma unroll
            for (int q = 0; q < 4; ++q) acc[j][q] = 0.f;

        // ---- kt loop, register double-buffered ----
        uint32_t Ah[2][4], Bf[2][4];
        ldsm4(Ah[0][0], Ah[0][1], Ah[0][2], Ah[0][3], aHiA);
        ldsm4(Bf[0][0], Bf[0][1], Bf[0][2], Bf[0][3], sbh + bOff);
        #pragma unroll
        for (int kt = 0; kt < 16; ++kt) {
            const int cur = kt & 1, nxt = cur ^ 1;
            if (kt < 15) {
                const uint32_t ka = (kt + 1) * 32;
                ldsm4(Ah[nxt][0], Ah[nxt][1], Ah[nxt][2], Ah[nxt][3], aHiA + ka);
                ldsm4(Bf[nxt][0], Bf[nxt][1], Bf[nxt][2], Bf[nxt][3], sbh + bOff + ka);
            }
            mma_f16(acc[0], Ah[cur][0], Ah[cur][1], Ah[cur][2], Ah[cur][3],
                    Bf[cur][0], Bf[cur][1]);
            mma_f16(acc[1], Ah[cur][0], Ah[cur][1], Ah[cur][2], Ah[cur][3],
                    Bf[cur][2], Bf[cur][3]);
        }

        // approx scores v = 2*dot - ||e||^2 ; gate into candidate lists
        float va0[4], va1[4];
        #pragma unroll
        for (int j = 0; j < 2; ++j) {
            #pragma unroll
            for (int e = 0; e < 2; ++e) {
                int q = 2 * j + e;
                int n = p * PANEL + 16 * wn + 8 * j + 2 * lr + e;
                float se = ssq_s[n];
                va0[q] = 2.0f * (acc[j][e] * INV_SCALE2) - se;
                va1[q] = 2.0f * (acc[j][2 + e] * INV_SCALE2) - se;
                bv0 = fmaxf(bv0, va0[q]);
                bv1 = fmaxf(bv1, va1[q]);
            }
        }
        bv0 = fmaxf(bv0, __shfl_xor_sync(0xffffffffu, bv0, 1));
        bv0 = fmaxf(bv0, __shfl_xor_sync(0xffffffffu, bv0, 2));
        bv1 = fmaxf(bv1, __shfl_xor_sync(0xffffffffu, bv1, 1));
        bv1 = fmaxf(bv1, __shfl_xor_sync(0xffffffffu, bv1, 2));
        const float th0 = bv0 - w0, th1 = bv1 - w1;
        #pragma unroll
        for (int q = 0; q < 4; ++q) {
            int n = p * PANEL + 16 * wn + 8 * (q >> 1) + 2 * lr + (q & 1);
            if (va0[q] >= th0) {
                int pos = atomicAdd(&ccnt[r0], 1);
                if (pos < MAXCAND) cidx[r0 * MAXCAND + pos] = n;
            }
            if (va1[q] >= th1) {
                int pos = atomicAdd(&ccnt[r0 + 8], 1);
                if (pos < MAXCAND) cidx[(r0 + 8) * MAXCAND + pos] = n;
            }
        }
    }
    __syncthreads();

    // ---- refine: exact fp32 rescore (reference rounding, first-index) ----
    for (int m = wid; m < BM; m += 32) {
        int cnt = ccnt[m];
        int bi;
        if (cnt == 1) {
            bi = cidx[m * MAXCAND];
        } else {
            const float assq = rssq_s[m];
            const float* xr = input + (n0 + m) * DIM;
            float bb = -3.4e38f;
            bi = 0x7fffffff;
            const bool full = (cnt > MAXCAND);
            const int ncand = full ? NEMBED : cnt;
            for (int c = 0; c < ncand; ++c) {
                int e = full ? c : cidx[m * MAXCAND + c];
                const float* er = g_embed_n + e * DIM;
                float dsum = 0.0f;
                #pragma unroll
                for (int i = 0; i < 8; ++i)
                    dsum += xr[lid + 32 * i] * er[lid + 32 * i];
                #pragma unroll
                for (int o = 16; o > 0; o >>= 1)
                    dsum += __shfl_xor_sync(0xffffffffu, dsum, o);
                float v = -((assq - 2.0f * dsum) + ssq_s[e]);
                if (v > bb || (v == bb && e < bi)) { bb = v; bi = e; }
            }
        }
        if (lid == 0) {
            best_s[m] = bi;
            ind_out[n0 + m] = (float)bi;
        }
    }
    __syncthreads();

    // ---- gather + out + MSE (float4) ----
    {
        float dsum = 0.0f;
        #pragma unroll 4
        for (int i = 0; i < 16; ++i) {
            int slot = tid + i * NTHREADS;       // 0..16383
            int m = slot >> 6, c4 = slot & 63;
            int e = best_s[m];
            float4 q = *(const float4*)(g_embed_n + e * DIM + c4 * 4);
            float4 x = *(const float4*)(input + (n0 + m) * DIM + c4 * 4);
            float4 o;
            float q1x = x.x + (q.x - x.x); o.x = (q.x + q1x) * 0.5f;
            float q1y = x.y + (q.y - x.y); o.y = (q.y + q1y) * 0.5f;
            float q1z = x.z + (q.z - x.z); o.z = (q.z + q1z) * 0.5f;
            float q1w = x.w + (q.w - x.w); o.w = (q.w + q1w) * 0.5f;
            *(float4*)(out + (n0 + m) * DIM + c4 * 4) = o;
            float dx = q.x - x.x, dy = q.y - x.y, dz = q.z - x.z, dw = q.w - x.w;
            dsum += dx * dx;
            dsum += dy * dy;
            dsum += dz * dz;
            dsum += dw * dw;
        }
        #pragma unroll
        for (int o = 16; o > 0; o >>= 1) dsum += __shfl_xor_sync(0xffffffffu, dsum, o);
        if (lid == 0) red[wid] = dsum;
    }
    __syncthreads();

    // ---- per-CTA diff partial + last-CTA loss epilogue ----
    __shared__ unsigned done_s;
    if (tid == 0) {
        float tot = 0.0f;
        #pragma unroll
        for (int k = 0; k < 32; ++k) tot += red[k];
        g_diff_arr[blockIdx.x] = tot;
        __threadfence();
        done_s = (atomicAdd(&g_count, 1u) == (unsigned)(NCTA - 1));
    }
    __syncthreads();
    if (done_s) {
        float colsum = 0.0f;
        if (tid < 256) {
            for (int r = 0; r < NEMBED; ++r)
                colsum += g_embed_n[r * DIM + tid];
            colsum = colsum * colsum;
        }
        #pragma unroll
        for (int o = 16; o > 0; o >>= 1)
            colsum += __shfl_xor_sync(0xffffffffu, colsum, o);
        if (lid == 0) red[wid] = colsum;     // warps >=8 contribute 0
        __syncthreads();
        float dpart = (tid < 512) ? g_diff_arr[tid] : 0.0f;
        #pragma unroll
        for (int o = 16; o > 0; o >>= 1)
            dpart += __shfl_xor_sync(0xffffffffu, dpart, o);
        __shared__ float dred[32];
        if (lid == 0) dred[wid] = dpart;
        float sq = (tid < 512) ? g_ssq[tid] : 0.0f;
        #pragma unroll
        for (int o = 16; o > 0; o >>= 1)
            sq += __shfl_xor_sync(0xffffffffu, sq, o);
        __shared__ float qred[32];
        if (lid == 0) qred[wid] = sq;
        __syncthreads();
        if (tid == 0) {
            float snorm2 = 0.0f, dtot = 0.0f, qtot = 0.0f;
            #pragma unroll
            for (int k = 0; k < 32; ++k) { snorm2 += red[k]; dtot += dred[k]; qtot += qred[k]; }
            float entropy = 2.0f * (float)NEMBED * qtot - 2.0f * snorm2;
            float diff = dtot * (1.0f / (float)OUT_ELEMS);
            loss_out[0] = diff - entropy * (1.0f / ((float)NEMBED * (float)NEMBED));
            g_count = 0u;                     // reset for next graph replay
        }
    }
}

// -------------------------------------------------------------- launch ----
extern "C" void kernel_launch(void* const* d_in, const int* in_sizes, int n_in,
                              void* d_out, int out_size) {
    const float* input     = (const float*)d_in[0];
    const float* embedding = (const float*)d_in[1];
    float* out  = (float*)d_out;
    float* loss = out + LOSS_OFF;
    float* ind  = out + IND_OFF;

    cudaFuncSetAttribute(main_kernel,
                         cudaFuncAttributeMaxDynamicSharedMemorySize, SMEM_BYTES);

    normalize_kernel<<<NEMBED, 256>>>(embedding);
    main_kernel<<<NCTA, NTHREADS, SMEM_BYTES>>>(input, out, ind, loss);
}

// round 14
// speedup vs baseline: 1.6558x; 1.6558x over previous
#include <cuda_runtime.h>
#include <cuda_fp16.h>
#include <cstdint>

#define DIM     256
#define NEMBED  512
#define NROWS   131072
#define OUT_ELEMS 33554432
#define LOSS_OFF  33554432
#define IND_OFF   33554433

#define BM 256
#define NCTA (NROWS / BM)         // 512
#define PANEL 64
#define NPANEL (NEMBED / PANEL)   // 8
#define KLD 264                   // halves per row; 528B stride
#define SCALE 2048.0f             // 2^11
#define INV_SCALE2 2.38418579e-07f // 2^-22 exact
#define NTHREADS 512
#define MAXCAND 16

#define ROWB (KLD * 2)            // 528 B
#define OFF_AHI  0                                   // 256*528 = 135168
#define OFF_B    (OFF_AHI + BM * ROWB)               // 135168
#define BSTAGE   (PANEL * ROWB)                      // 33792
#define OFF_SSQ  (OFF_B + 2 * BSTAGE)                // 202752 (512 f)
#define OFF_RSSQ (OFF_SSQ + NEMBED * 4)              // 204800 (256 f)
#define OFF_CIDX (OFF_RSSQ + BM * 4)                 // 205824 (256*16 i)
#define OFF_CCNT (OFF_CIDX + BM * MAXCAND * 4)       // 222208 (256 i)
#define OFF_BEST (OFF_CCNT + BM * 4)                 // 223232 (256 i)
#define OFF_RED  (OFF_BEST + BM * 4)                 // 224256 (16 f)
#define SMEM_BYTES (OFF_RED + 64)                    // 224320

__device__ float  g_embed_n[NEMBED * DIM];
__device__ __half g_bh16[NEMBED * DIM];
__device__ float  g_ssq[NEMBED];
__device__ float  g_diff_arr[NCTA];
__device__ unsigned g_count;      // static-init 0; last CTA resets to 0

__device__ __forceinline__ uint32_t smem_u32(const void* p) {
    uint32_t a;
    asm("{ .reg .u64 t; cvta.to.shared.u64 t, %1; cvt.u32.u64 %0, t; }" : "=r"(a) : "l"(p));
    return a;
}
__device__ __forceinline__ void mma_f16(float* d, uint32_t a0, uint32_t a1,
                                        uint32_t a2, uint32_t a3,
                                        uint32_t b0, uint32_t b1) {
    asm volatile(
        "mma.sync.aligned.m16n8k16.row.col.f32.f16.f16.f32 "
        "{%0,%1,%2,%3}, {%4,%5,%6,%7}, {%8,%9}, {%0,%1,%2,%3};"
        : "+f"(d[0]), "+f"(d[1]), "+f"(d[2]), "+f"(d[3])
        : "r"(a0), "r"(a1), "r"(a2), "r"(a3), "r"(b0), "r"(b1));
}
__device__ __forceinline__ void ldsm4(uint32_t& r0, uint32_t& r1,
                                      uint32_t& r2, uint32_t& r3, uint32_t addr) {
    asm volatile("ldmatrix.sync.aligned.m8n8.x4.shared.b16 {%0,%1,%2,%3}, [%4];"
                 : "=r"(r0), "=r"(r1), "=r"(r2), "=r"(r3) : "r"(addr));
}
__device__ __forceinline__ void cp16(uint32_t dst, const void* src) {
    asm volatile("cp.async.cg.shared.global [%0], [%1], 16;" :: "r"(dst), "l"(src) : "memory");
}
#define CP_COMMIT() asm volatile("cp.async.commit_group;" ::: "memory")
#define CP_WAIT0()  asm volatile("cp.async.wait_group 0;" ::: "memory")

// ------------------------------------- normalize + fp16 hi (scaled) ----
__global__ void normalize_kernel(const float* __restrict__ emb) {
    __shared__ float w[8];
    int r = blockIdx.x, t = threadIdx.x;
    float v = emb[r * DIM + t];
    float s = v * v;
    #pragma unroll
    for (int o = 16; o > 0; o >>= 1) s += __shfl_xor_sync(0xffffffffu, s, o);
    if ((t & 31) == 0) w[t >> 5] = s;
    __syncthreads();
    float sum = 0.0f;
    #pragma unroll
    for (int k = 0; k < 8; ++k) sum += w[k];
    float en = __fdiv_rn(v, __fsqrt_rn(sum));
    g_embed_n[r * DIM + t] = en;
    g_bh16[r * DIM + t] = __float2half_rn(en * SCALE);

    float s2 = en * en;
    #pragma unroll
    for (int o = 16; o > 0; o >>= 1) s2 += __shfl_xor_sync(0xffffffffu, s2, o);
    __syncthreads();
    if ((t & 31) == 0) w[t >> 5] = s2;
    __syncthreads();
    if (t == 0) {
        float tot = 0.0f;
        #pragma unroll
        for (int k = 0; k < 8; ++k) tot += w[k];
        g_ssq[r] = tot;
    }
}

// ------------------------------------------------------------- main ----
__global__ void __launch_bounds__(NTHREADS, 1)
main_kernel(const float* __restrict__ input,
            float* __restrict__ out,
            float* __restrict__ ind_out,
            float* __restrict__ loss_out) {
    extern __shared__ char sm[];
    const uint32_t smb = smem_u32(sm);
    __half* ahi   = (__half*)(sm + OFF_AHI);
    float*  ssq_s = (float*)(sm + OFF_SSQ);
    float*  rssq_s= (float*)(sm + OFF_RSSQ);
    int*    cidx  = (int*)(sm + OFF_CIDX);
    int*    ccnt  = (int*)(sm + OFF_CCNT);
    int*    best_s= (int*)(sm + OFF_BEST);
    float*  red   = (float*)(sm + OFF_RED);

    const int tid = threadIdx.x;
    const int wid = tid >> 5;
    const int lid = tid & 31;
    const int lq  = lid >> 2;
    const int lr  = lid & 3;
    const size_t n0 = (size_t)blockIdx.x * BM;

    // ---- prefetch B panel 0 (hi) into stage 0: 64 rows x 32 chunks ----
    #pragma unroll
    for (int i = 0; i < 4; ++i) {
        int c = tid + i * NTHREADS;              // 0..2047
        int r = c >> 5, ch = c & 31;
        cp16(smb + OFF_B + r * ROWB + ch * 16, g_bh16 + r * DIM + ch * 8);
    }
    CP_COMMIT();

    // ---- load input tile (256 rows), scale, fp16 hi split ----
    #pragma unroll
    for (int i = 0; i < 32; ++i) {
        int slot = tid + i * NTHREADS;           // 0..16383
        int m = slot >> 6, c4 = slot & 63;
        float4 v = *(const float4*)(input + (n0 + m) * DIM + c4 * 4);
        __half hx = __float2half_rn(v.x * SCALE);
        __half hy = __float2half_rn(v.y * SCALE);
        __half hz = __float2half_rn(v.z * SCALE);
        __half hw = __float2half_rn(v.w * SCALE);
        int ho = m * KLD + c4 * 4;
        *(__half2*)(ahi + ho)     = __halves2half2(hx, hy);
        *(__half2*)(ahi + ho + 2) = __halves2half2(hz, hw);
    }
    ssq_s[tid] = g_ssq[tid];
    if (tid < BM) ccnt[tid] = 0;

    // ---- per-row ||x||^2 — float4 loads, IDENTICAL sequential add order ----
    {
        int m = tid >> 1, half = tid & 1;        // 512 threads -> 256 rows
        const float* xr = input + (n0 + m) * DIM + half * 128;
        float s = 0.0f;
        #pragma unroll 8
        for (int k4 = 0; k4 < 32; ++k4) {
            float4 v = *(const float4*)(xr + k4 * 4);
            s += v.x * v.x;
            s += v.y * v.y;
            s += v.z * v.z;
            s += v.w * v.w;
        }
        s += __shfl_xor_sync(0xffffffffu, s, 1);
        if (half == 0) rssq_s[m] = s;
    }
    __syncthreads();

    const int r0 = wid * 16 + lq;
    // gate width: >2x the rigorous 1-term error bound
    const float w0 = 0.0025f * __fsqrt_rn(rssq_s[r0])     + 0.003f;
    const float w1 = 0.0025f * __fsqrt_rn(rssq_s[r0 + 8]) + 0.003f;

    // ---- ldmatrix addresses ----
    const int rowin = lid & 7;
    const int mi    = lid >> 3;
    const int aRow  = wid * 16 + rowin + 8 * (mi & 1);
    const uint32_t aHiA = smb + OFF_AHI + (uint32_t)(aRow * ROWB + (mi >> 1) * 16);
    uint32_t bOff[4];
    #pragma unroll
    for (int q = 0; q < 4; ++q)
        bOff[q] = (uint32_t)((8 * (2 * q + (mi >> 1)) + rowin) * ROWB + (mi & 1) * 16);

    float bv0 = -3.4e38f, bv1 = -3.4e38f;

    for (int p = 0; p < NPANEL; ++p) {
        CP_WAIT0();
        __syncthreads();
        if (p + 1 < NPANEL) {
            const int np = p + 1, st = np & 1;
            #pragma unroll
            for (int i = 0; i < 4; ++i) {
                int c = tid + i * NTHREADS;
                int r = c >> 5, ch = c & 31;
                cp16(smb + OFF_B + st * BSTAGE + r * ROWB + ch * 16,
                     g_bh16 + (np * PANEL + r) * DIM + ch * 8);
            }
            CP_COMMIT();
        }

        const uint32_t sbh = smb + OFF_B + (p & 1) * BSTAGE;

        float acc[8][4];
        #pragma unroll
        for (int j = 0; j < 8; ++j)
            #pragma unroll
            for (int q = 0; q < 4; ++q) acc[j][q] = 0.f;

        // ---- kt loop with manual register double-buffer ----
        uint32_t Ah[2][4], Bf[2][16];
        ldsm4(Ah[0][0], Ah[0][1], Ah[0][2], Ah[0][3], aHiA);
        #pragma unroll
        for (int q = 0; q < 4; ++q)
            ldsm4(Bf[0][4 * q], Bf[0][4 * q + 1], Bf[0][4 * q + 2], Bf[0][4 * q + 3],
                  sbh + bOff[q]);
        #pragma unroll
        for (int kt = 0; kt < 16; ++kt) {
            const int cur = kt & 1, nxt = cur ^ 1;
            if (kt < 15) {
                const uint32_t ka = (kt + 1) * 32;
                ldsm4(Ah[nxt][0], Ah[nxt][1], Ah[nxt][2], Ah[nxt][3], aHiA + ka);
                #pragma unroll
                for (int q = 0; q < 4; ++q)
                    ldsm4(Bf[nxt][4 * q], Bf[nxt][4 * q + 1],
                          Bf[nxt][4 * q + 2], Bf[nxt][4 * q + 3],
                          sbh + bOff[q] + ka);
            }
            #pragma unroll
            for (int j = 0; j < 8; ++j)
                mma_f16(acc[j], Ah[cur][0], Ah[cur][1], Ah[cur][2], Ah[cur][3],
                        Bf[cur][2 * j], Bf[cur][2 * j + 1]);
        }

        // approx scores v = 2*dot - ||e||^2 ; gate into candidate lists
        float va0[16], va1[16];
        #pragma unroll
        for (int j = 0; j < 8; ++j) {
            #pragma unroll
            for (int e = 0; e < 2; ++e) {
                int q = 2 * j + e;
                int n = p * PANEL + 8 * j + 2 * lr + e;
                float se = ssq_s[n];
                va0[q] = 2.0f * (acc[j][e] * INV_SCALE2) - se;
                va1[q] = 2.0f * (acc[j][2 + e] * INV_SCALE2) - se;
                bv0 = fmaxf(bv0, va0[q]);
                bv1 = fmaxf(bv1, va1[q]);
            }
        }
        bv0 = fmaxf(bv0, __shfl_xor_sync(0xffffffffu, bv0, 1));
        bv0 = fmaxf(bv0, __shfl_xor_sync(0xffffffffu, bv0, 2));
        bv1 = fmaxf(bv1, __shfl_xor_sync(0xffffffffu, bv1, 1));
        bv1 = fmaxf(bv1, __shfl_xor_sync(0xffffffffu, bv1, 2));
        const float th0 = bv0 - w0, th1 = bv1 - w1;
        #pragma unroll
        for (int q = 0; q < 16; ++q) {
            int n = p * PANEL + 8 * (q >> 1) + 2 * lr + (q & 1);
            if (va0[q] >= th0) {
                int pos = atomicAdd(&ccnt[r0], 1);
                if (pos < MAXCAND) cidx[r0 * MAXCAND + pos] = n;
            }
            if (va1[q] >= th1) {
                int pos = atomicAdd(&ccnt[r0 + 8], 1);
                if (pos < MAXCAND) cidx[(r0 + 8) * MAXCAND + pos] = n;
            }
        }
    }
    __syncthreads();

    // ---- refine: exact fp32 rescore only when >1 candidate ----
    for (int m = wid; m < BM; m += 16) {
        int cnt = ccnt[m];
        int bi;
        if (cnt == 1) {
            bi = cidx[m * MAXCAND];
        } else {
            const float assq = rssq_s[m];
            const float* xr = input + (n0 + m) * DIM;
            float bb = -3.4e38f;
            bi = 0x7fffffff;
            const bool full = (cnt > MAXCAND);
            const int ncand = full ? NEMBED : cnt;
            for (int c = 0; c < ncand; ++c) {
                int e = full ? c : cidx[m * MAXCAND + c];
                const float* er = g_embed_n + e * DIM;
                float dsum = 0.0f;
                #pragma unroll
                for (int i = 0; i < 8; ++i)
                    dsum += xr[lid + 32 * i] * er[lid + 32 * i];
                #pragma unroll
                for (int o = 16; o > 0; o >>= 1)
                    dsum += __shfl_xor_sync(0xffffffffu, dsum, o);
                float v = -((assq - 2.0f * dsum) + ssq_s[e]);
                if (v > bb || (v == bb && e < bi)) { bb = v; bi = e; }
            }
        }
        if (lid == 0) {
            best_s[m] = bi;
            ind_out[n0 + m] = (float)bi;
        }
    }
    __syncthreads();

    // ---- gather + out + MSE (float4; element math identical) ----
    {
        float dsum = 0.0f;
        #pragma unroll 4
        for (int i = 0; i < 32; ++i) {
            int slot = tid + i * NTHREADS;       // 0..16383
            int m = slot >> 6, c4 = slot & 63;
            int e = best_s[m];
            float4 q = *(const float4*)(g_embed_n + e * DIM + c4 * 4);
            float4 x = *(const float4*)(input + (n0 + m) * DIM + c4 * 4);
            float4 o;
            float q1x = x.x + (q.x - x.x); o.x = (q.x + q1x) * 0.5f;
            float q1y = x.y + (q.y - x.y); o.y = (q.y + q1y) * 0.5f;
            float q1z = x.z + (q.z - x.z); o.z = (q.z + q1z) * 0.5f;
            float q1w = x.w + (q.w - x.w); o.w = (q.w + q1w) * 0.5f;
            *(float4*)(out + (n0 + m) * DIM + c4 * 4) = o;
            float dx = q.x - x.x, dy = q.y - x.y, dz = q.z - x.z, dw = q.w - x.w;
            dsum += dx * dx;
            dsum += dy * dy;
            dsum += dz * dz;
            dsum += dw * dw;
        }
        #pragma unroll
        for (int o = 16; o > 0; o >>= 1) dsum += __shfl_xor_sync(0xffffffffu, dsum, o);
        if (lid == 0) red[wid] = dsum;
    }
    __syncthreads();

    // ---- per-CTA diff partial + last-CTA loss epilogue ----
    __shared__ unsigned done_s;
    if (tid == 0) {
        float tot = 0.0f;
        #pragma unroll
        for (int k = 0; k < 16; ++k) tot += red[k];
        g_diff_arr[blockIdx.x] = tot;
        __threadfence();
        done_s = (atomicAdd(&g_count, 1u) == (unsigned)(NCTA - 1));
    }
    __syncthreads();
    if (done_s) {
        float colsum = 0.0f;
        if (tid < 256) {
            for (int r = 0; r < NEMBED; ++r)
                colsum += g_embed_n[r * DIM + tid];
            colsum = colsum * colsum;
        }
        #pragma unroll
        for (int o = 16; o > 0; o >>= 1)
            colsum += __shfl_xor_sync(0xffffffffu, colsum, o);
        if (lid == 0) red[wid] = colsum;
        __syncthreads();
        float dpart = g_diff_arr[tid];
        #pragma unroll
        for (int o = 16; o > 0; o >>= 1)
            dpart += __shfl_xor_sync(0xffffffffu, dpart, o);
        __shared__ float dred[16];
        if (lid == 0) dred[wid] = dpart;
        float sq = g_ssq[tid];
        #pragma unroll
        for (int o = 16; o > 0; o >>= 1)
            sq += __shfl_xor_sync(0xffffffffu, sq, o);
        __shared__ float qred[16];
        if (lid == 0) qred[wid] = sq;
        __syncthreads();
        if (tid == 0) {
            float snorm2 = 0.0f, dtot = 0.0f, qtot = 0.0f;
            #pragma unroll
            for (int k = 0; k < 16; ++k) { snorm2 += red[k]; dtot += dred[k]; qtot += qred[k]; }
            float entropy = 2.0f * (float)NEMBED * qtot - 2.0f * snorm2;
            float diff = dtot * (1.0f / (float)OUT_ELEMS);
            loss_out[0] = diff - entropy * (1.0f / ((float)NEMBED * (float)NEMBED));
            g_count = 0u;                     // reset for next graph replay
        }
    }
}

// -------------------------------------------------------------- launch ----
extern "C" void kernel_launch(void* const* d_in, const int* in_sizes, int n_in,
                              void* d_out, int out_size) {
    const float* input     = (const float*)d_in[0];
    const float* embedding = (const float*)d_in[1];
    float* out  = (float*)d_out;
    float* loss = out + LOSS_OFF;
    float* ind  = out + IND_OFF;

    cudaFuncSetAttribute(main_kernel,
                         cudaFuncAttributeMaxDynamicSharedMemorySize, SMEM_BYTES);

    normalize_kernel<<<NEMBED, 256>>>(embedding);
    main_kernel<<<NCTA, NTHREADS, SMEM_BYTES>>>(input, out, ind, loss);
}